// round 1
// baseline (speedup 1.0000x reference)
#include <cuda_runtime.h>
#include <cuda_bf16.h>
#include <cstring>

// Problem dims
#define EMBED 512
#define FFN   64
#define NQ    16
#define NTOK  65536   // 16 * 4096

// GEMM tiling
#define TOKB  128     // tokens per block
#define EB    128     // embed outputs per block
#define KD    64      // reduction dim (= FFN)
#define W2S   129     // padded smem stride for W2^T tile

// 16 MiB scratch for relu(H)
__device__ float g_h[(size_t)NTOK * FFN];

struct alignas(8) F2 { float x, y; };

__device__ __forceinline__ F2 ffma2(F2 a, F2 b, F2 c) {
    unsigned long long ua, ub, uc, ud;
    memcpy(&ua, &a, 8); memcpy(&ub, &b, 8); memcpy(&uc, &c, 8);
    asm("fma.rn.f32x2 %0, %1, %2, %3;" : "=l"(ud) : "l"(ua), "l"(ub), "l"(uc));
    F2 d; memcpy(&d, &ud, 8);
    return d;
}

// ---------------------------------------------------------------------------
// Kernel A: H[t][f] = relu( sum_q cos(x[t][q])*cos(theta[q]) * W1[f][q] + b1[f] )
// One thread per token. 256 blocks x 256 threads.
// ---------------------------------------------------------------------------
__global__ void __launch_bounds__(256) h_kernel(
    const float* __restrict__ x,
    const float* __restrict__ theta,
    const float* __restrict__ W1,
    const float* __restrict__ b1)
{
    __shared__ float ct[NQ];
    __shared__ float w1s[FFN * NQ];
    __shared__ float b1s[FFN];

    int tid = threadIdx.x;
    if (tid < NQ) ct[tid] = cosf(theta[tid]);
    for (int i = tid; i < FFN * NQ; i += 256) w1s[i] = W1[i];
    if (tid < FFN) b1s[tid] = b1[tid];
    __syncthreads();

    int t = blockIdx.x * 256 + tid;
    const float4* xr = (const float4*)(x + (size_t)t * EMBED);

    float z[NQ];
#pragma unroll
    for (int i = 0; i < 4; i++) {
        float4 v = xr[i];
        z[4*i + 0] = cosf(v.x) * ct[4*i + 0];
        z[4*i + 1] = cosf(v.y) * ct[4*i + 1];
        z[4*i + 2] = cosf(v.z) * ct[4*i + 2];
        z[4*i + 3] = cosf(v.w) * ct[4*i + 3];
    }

    float4* Hr = (float4*)(g_h + (size_t)t * FFN);
#pragma unroll
    for (int f4 = 0; f4 < FFN / 4; f4++) {
        float4 hv;
        float s[4];
#pragma unroll
        for (int c = 0; c < 4; c++) {
            int f = f4 * 4 + c;
            float acc = b1s[f];
#pragma unroll
            for (int q = 0; q < NQ; q++)
                acc = fmaf(z[q], w1s[f * NQ + q], acc);
            s[c] = fmaxf(acc, 0.0f);
        }
        hv.x = s[0]; hv.y = s[1]; hv.z = s[2]; hv.w = s[3];
        Hr[f4] = hv;
    }
}

// ---------------------------------------------------------------------------
// Kernel B: out[t][e] = sum_k H[t][k] * W2[e][k] + b2[e]
// Block tile: 128 tokens x 128 e, K=64 fully in smem.
// Thread tile: 4 token-pairs x 8 e, f32x2 accumulators (fma.rn.f32x2).
// ---------------------------------------------------------------------------
__global__ void __launch_bounds__(256, 2) gemm_kernel(
    const float* __restrict__ W2,
    const float* __restrict__ b2,
    float* __restrict__ out)
{
    extern __shared__ float smem[];
    float* hTf = smem;                 // [KD][TOKB]  = 64*128 floats (32 KB)
    float* w2T = smem + KD * TOKB;     // [KD][W2S]   = 64*129 floats (33 KB)

    int tid = threadIdx.x;
    int gt0 = blockIdx.x * TOKB;
    int e0  = blockIdx.y * EB;

    // Load H tile: hTf[k][t_loc] = H[gt0+t_loc][k] (transpose).
    // Thread: t_loc = tid&127, k-half = (tid>>7)*32. Coalesced-enough LDG.128,
    // conflict-free STS (consecutive t_loc across lanes).
    {
        int t_loc = tid & 127;
        int kh = (tid >> 7) * 32;
        const float4* src = (const float4*)(g_h + (size_t)(gt0 + t_loc) * FFN + kh);
#pragma unroll
        for (int kk = 0; kk < 32; kk += 4) {
            float4 v = src[kk >> 2];
            hTf[(kh + kk + 0) * TOKB + t_loc] = v.x;
            hTf[(kh + kk + 1) * TOKB + t_loc] = v.y;
            hTf[(kh + kk + 2) * TOKB + t_loc] = v.z;
            hTf[(kh + kk + 3) * TOKB + t_loc] = v.w;
        }
    }

    // Load W2 tile: w2T[k][r] = W2[e0+r][k] (transpose, padded stride 129).
    {
        int r  = tid >> 1;
        int kh = (tid & 1) * 32;
        const float4* src = (const float4*)(W2 + (size_t)(e0 + r) * KD + kh);
#pragma unroll
        for (int kk = 0; kk < 32; kk += 4) {
            float4 v = src[kk >> 2];
            w2T[(kh + kk + 0) * W2S + r] = v.x;
            w2T[(kh + kk + 1) * W2S + r] = v.y;
            w2T[(kh + kk + 2) * W2S + r] = v.z;
            w2T[(kh + kk + 3) * W2S + r] = v.w;
        }
    }
    __syncthreads();

    int tx = tid & 15;          // e direction
    int ty = tid >> 4;          // token-pair direction (0..15)

    F2 acc[4][8];
#pragma unroll
    for (int j = 0; j < 8; j++) {
        float bv = b2[e0 + j * 16 + tx];
#pragma unroll
        for (int i = 0; i < 4; i++) { acc[i][j].x = bv; acc[i][j].y = bv; }
    }

    const F2* hT2 = (const F2*)hTf;   // [KD][TOKB/2] token pairs

#pragma unroll 4
    for (int k = 0; k < KD; k++) {
        F2 hp[4];
#pragma unroll
        for (int i = 0; i < 4; i++)
            hp[i] = hT2[k * (TOKB / 2) + i * 16 + ty];

        F2 wp[8];
#pragma unroll
        for (int j = 0; j < 8; j++) {
            float w = w2T[k * W2S + j * 16 + tx];
            wp[j].x = w; wp[j].y = w;
        }

#pragma unroll
        for (int i = 0; i < 4; i++)
#pragma unroll
            for (int j = 0; j < 8; j++)
                acc[i][j] = ffma2(hp[i], wp[j], acc[i][j]);
    }

    // Epilogue: token pair p = i*16+ty -> rows 2p, 2p+1. Coalesced across tx.
#pragma unroll
    for (int i = 0; i < 4; i++) {
        int t = gt0 + (i * 16 + ty) * 2;
#pragma unroll
        for (int j = 0; j < 8; j++) {
            int e = e0 + j * 16 + tx;
            out[(size_t)t * EMBED + e]       = acc[i][j].x;
            out[(size_t)(t + 1) * EMBED + e] = acc[i][j].y;
        }
    }
}

// ---------------------------------------------------------------------------
extern "C" void kernel_launch(void* const* d_in, const int* in_sizes, int n_in,
                              void* d_out, int out_size)
{
    // Identify inputs by element count (all distinct) for robustness.
    const float *x = nullptr, *theta = nullptr, *W1 = nullptr,
                *b1 = nullptr, *W2 = nullptr, *b2 = nullptr;
    for (int i = 0; i < n_in; i++) {
        switch (in_sizes[i]) {
            case NTOK * EMBED: x     = (const float*)d_in[i]; break;  // 33554432
            case NQ:           theta = (const float*)d_in[i]; break;  // 16
            case FFN * NQ:     W1    = (const float*)d_in[i]; break;  // 1024
            case FFN:          b1    = (const float*)d_in[i]; break;  // 64
            case EMBED * FFN:  W2    = (const float*)d_in[i]; break;  // 32768
            case EMBED:        b2    = (const float*)d_in[i]; break;  // 512
            default: break;
        }
    }
    float* out = (float*)d_out;

    static int smem_set = 0;
    const int smem_bytes = (KD * TOKB + KD * W2S) * (int)sizeof(float); // 65792
    if (!smem_set) {
        cudaFuncSetAttribute(gemm_kernel,
                             cudaFuncAttributeMaxDynamicSharedMemorySize,
                             smem_bytes);
        smem_set = 1;
    }

    h_kernel<<<NTOK / 256, 256>>>(x, theta, W1, b1);
    gemm_kernel<<<dim3(NTOK / TOKB, EMBED / EB), 256, smem_bytes>>>(W2, b2, out);
}

// round 4
// speedup vs baseline: 1.3112x; 1.3112x over previous
#include <cuda_runtime.h>
#include <cuda_bf16.h>
#include <cstdint>

// Problem dims
#define EMBED 512
#define FFN   64
#define NQ    16
#define NTOK  65536   // 16 * 4096

// GEMM tiling
#define MT 128              // tokens per CTA
#define NT 128              // embed outputs per CTA
#define ASTRIDE 272         // A smem row stride bytes (256B data + 16B pad)
#define BSTRIDE 400         // B smem row stride bytes (384B data + 16B pad)
#define SMEM_A_BYTES (MT * ASTRIDE)            // 34816
#define SMEM_B_BYTES (NT * BSTRIDE)            // 51200
#define SMEM_TOTAL   (SMEM_A_BYTES + SMEM_B_BYTES + 512)  // + bias

// H in bf16 split form: per token 128 bf16 = [Hh(64) | Hl(64)], 16 MiB
__device__ __align__(16) __nv_bfloat16 g_hb[(size_t)NTOK * 128];

__device__ __forceinline__ uint32_t smem_u32(const void* p) {
    uint32_t a;
    asm("{ .reg .u64 t; cvta.to.shared.u64 t, %1; cvt.u32.u64 %0, t; }"
        : "=r"(a) : "l"(p));
    return a;
}

#define LDSM_X4(r0, r1, r2, r3, addr) \
    asm volatile("ldmatrix.sync.aligned.m8n8.x4.shared.b16 {%0,%1,%2,%3}, [%4];" \
                 : "=r"(r0), "=r"(r1), "=r"(r2), "=r"(r3) : "r"(addr))

#define MMA16816(d, a0, a1, a2, a3, b0, b1) \
    asm volatile("mma.sync.aligned.m16n8k16.row.col.f32.bf16.bf16.f32 " \
                 "{%0,%1,%2,%3}, {%4,%5,%6,%7}, {%8,%9}, {%0,%1,%2,%3};" \
                 : "+f"((d)[0]), "+f"((d)[1]), "+f"((d)[2]), "+f"((d)[3]) \
                 : "r"(a0), "r"(a1), "r"(a2), "r"(a3), "r"(b0), "r"(b1))

// ---------------------------------------------------------------------------
// Kernel A: H[t][f] = relu( sum_q cos(x[t][q])*cos(theta[q]) * W1[f][q] + b1[f] )
// Emits bf16 two-term split per token: [bf16(H) (64) | bf16(H - bf16(H)) (64)]
// ---------------------------------------------------------------------------
__global__ void __launch_bounds__(256) h_kernel(
    const float* __restrict__ x,
    const float* __restrict__ theta,
    const float* __restrict__ W1,
    const float* __restrict__ b1)
{
    __shared__ float ct[NQ];
    __shared__ float w1s[FFN * NQ];
    __shared__ float b1s[FFN];

    int tid = threadIdx.x;
    if (tid < NQ) ct[tid] = cosf(theta[tid]);
    for (int i = tid; i < FFN * NQ; i += 256) w1s[i] = W1[i];
    if (tid < FFN) b1s[tid] = b1[tid];
    __syncthreads();

    int t = blockIdx.x * 256 + tid;
    const float4* xr = (const float4*)(x + (size_t)t * EMBED);

    float z[NQ];
#pragma unroll
    for (int i = 0; i < 4; i++) {
        float4 v = xr[i];
        z[4*i + 0] = cosf(v.x) * ct[4*i + 0];
        z[4*i + 1] = cosf(v.y) * ct[4*i + 1];
        z[4*i + 2] = cosf(v.z) * ct[4*i + 2];
        z[4*i + 3] = cosf(v.w) * ct[4*i + 3];
    }

    uint32_t hh[32], hl[32];
#pragma unroll
    for (int p = 0; p < 32; p++) {
        int f0 = 2 * p;
        float a0 = b1s[f0], a1 = b1s[f0 + 1];
#pragma unroll
        for (int q = 0; q < NQ; q++) {
            a0 = fmaf(z[q], w1s[f0 * NQ + q], a0);
            a1 = fmaf(z[q], w1s[(f0 + 1) * NQ + q], a1);
        }
        a0 = fmaxf(a0, 0.0f);
        a1 = fmaxf(a1, 0.0f);
        __nv_bfloat16 h0 = __float2bfloat16(a0);
        __nv_bfloat16 h1 = __float2bfloat16(a1);
        __nv_bfloat16 l0 = __float2bfloat16(a0 - __bfloat162float(h0));
        __nv_bfloat16 l1 = __float2bfloat16(a1 - __bfloat162float(h1));
        hh[p] = (uint32_t)__bfloat16_as_ushort(h0) | ((uint32_t)__bfloat16_as_ushort(h1) << 16);
        hl[p] = (uint32_t)__bfloat16_as_ushort(l0) | ((uint32_t)__bfloat16_as_ushort(l1) << 16);
    }

    uint4* dst = (uint4*)(g_hb + (size_t)t * 128);
#pragma unroll
    for (int i = 0; i < 8; i++)
        dst[i] = make_uint4(hh[4*i], hh[4*i+1], hh[4*i+2], hh[4*i+3]);
#pragma unroll
    for (int i = 0; i < 8; i++)
        dst[8 + i] = make_uint4(hl[4*i], hl[4*i+1], hl[4*i+2], hl[4*i+3]);
}

// ---------------------------------------------------------------------------
// Kernel B (HMMA): out[t][e] = sum_k H[t][k]*W2[e][k] + b2[e]
// K=192 three-term bf16 split: A k-blocks [Hh, Hh, Hl], B k-blocks [Wh, Wl, Wh].
// CTA: 128 tokens x 128 e, 8 warps (4M x 2N), warp tile 32x64.
// B is [n][k] row-major == col-major KxN: plain (non-trans) ldmatrix.
// ---------------------------------------------------------------------------
__global__ void __launch_bounds__(256, 2) gemm_hmma(
    const float* __restrict__ W2,
    const float* __restrict__ b2,
    float* __restrict__ out)
{
    extern __shared__ char dsm[];
    char* sA  = dsm;                                   // [128][272B]: [Hh|Hl]
    char* sB  = dsm + SMEM_A_BYTES;                    // [128][400B]: [Wh|Wl|Wh]
    float* b2s = (float*)(dsm + SMEM_A_BYTES + SMEM_B_BYTES);

    uint32_t sAu = smem_u32(sA);
    uint32_t sBu = smem_u32(sB);

    int tid = threadIdx.x;
    int gt0 = blockIdx.x * MT;
    int e0  = blockIdx.y * NT;

    // --- Load A tile: 2 threads per token row, 128B halves ---
    {
        int row = tid >> 1, half = tid & 1;
        const uint4* src = (const uint4*)(g_hb + (size_t)(gt0 + row) * 128 + half * 64);
        uint4* dst = (uint4*)(sA + row * ASTRIDE + half * 128);
#pragma unroll
        for (int i = 0; i < 8; i++) dst[i] = src[i];
    }

    // --- Load + split B tile: one thread per embed row ---
    if (tid < NT) {
        const float4* wsrc = (const float4*)(W2 + (size_t)(e0 + tid) * FFN);
        uint4 vh[8], vl[8];
#pragma unroll
        for (int i = 0; i < 8; i++) {
            float4 va = wsrc[2*i], vb = wsrc[2*i + 1];
            float f[8] = {va.x, va.y, va.z, va.w, vb.x, vb.y, vb.z, vb.w};
            uint32_t hb[8], lb[8];
#pragma unroll
            for (int c = 0; c < 8; c++) {
                __nv_bfloat16 h = __float2bfloat16(f[c]);
                __nv_bfloat16 l = __float2bfloat16(f[c] - __bfloat162float(h));
                hb[c] = __bfloat16_as_ushort(h);
                lb[c] = __bfloat16_as_ushort(l);
            }
            vh[i] = make_uint4(hb[0] | (hb[1] << 16), hb[2] | (hb[3] << 16),
                               hb[4] | (hb[5] << 16), hb[6] | (hb[7] << 16));
            vl[i] = make_uint4(lb[0] | (lb[1] << 16), lb[2] | (lb[3] << 16),
                               lb[4] | (lb[5] << 16), lb[6] | (lb[7] << 16));
        }
        char* rb = sB + tid * BSTRIDE;
#pragma unroll
        for (int i = 0; i < 8; i++) ((uint4*)rb)[i]         = vh[i];   // Wh
#pragma unroll
        for (int i = 0; i < 8; i++) ((uint4*)(rb + 128))[i] = vl[i];   // Wl
#pragma unroll
        for (int i = 0; i < 8; i++) ((uint4*)(rb + 256))[i] = vh[i];   // Wh

        b2s[tid] = b2[e0 + tid];
    }
    __syncthreads();

    int wid = tid >> 5, l = tid & 31;
    int wm = wid & 3;        // M block (32 rows)
    int wn = wid >> 2;       // N block (64 cols)

    // Accumulators [mt][nt][4], bias-initialized
    float acc[2][8][4];
    {
        int cb = wn * 64 + (l & 3) * 2;
#pragma unroll
        for (int nt = 0; nt < 8; nt++) {
            float bv0 = b2s[cb + nt * 8];
            float bv1 = b2s[cb + nt * 8 + 1];
#pragma unroll
            for (int mt = 0; mt < 2; mt++) {
                acc[mt][nt][0] = bv0; acc[mt][nt][1] = bv1;
                acc[mt][nt][2] = bv0; acc[mt][nt][3] = bv1;
            }
        }
    }

    // ldmatrix per-lane base addresses
    // A: lanes 0-15 -> rows 0-15 at k0; lanes 16-31 -> same rows at k0+8 elems
    uint32_t aBase = sAu + (uint32_t)(wm * 32 + (l & 15)) * ASTRIDE + ((l >> 4) << 4);
    // B (non-trans; [n][k] rows): lanes 0-7 n0-7 @k0; 8-15 n0-7 @k+8; 16-23 n8-15 @k0; 24-31 n8-15 @k+8
    uint32_t bRow  = (uint32_t)(wn * 64 + (l & 7) + ((l >> 4) << 3));
    uint32_t bBase = sBu + bRow * BSTRIDE + (((l >> 3) & 1) << 4);

#pragma unroll
    for (int ks = 0; ks < 12; ks++) {
        int term = ks >> 2;
        int kin  = (ks & 3) * 32;                      // byte offset within 64-elem block
        uint32_t aOff = (uint32_t)((term == 2 ? 128 : 0) + kin);
        uint32_t bOff = (uint32_t)(term * 128 + kin);

        uint32_t a[2][4];
#pragma unroll
        for (int mt = 0; mt < 2; mt++)
            LDSM_X4(a[mt][0], a[mt][1], a[mt][2], a[mt][3],
                    aBase + (uint32_t)(mt * 16) * ASTRIDE + aOff);

        uint32_t b[8][2];
#pragma unroll
        for (int j = 0; j < 4; j++) {
            uint32_t r0, r1, r2, r3;
            LDSM_X4(r0, r1, r2, r3,
                    bBase + (uint32_t)(j * 16) * BSTRIDE + bOff);
            b[2*j][0]   = r0;  b[2*j][1]   = r1;   // n group 2j:   b0(k0-7), b1(k8-15)
            b[2*j+1][0] = r2;  b[2*j+1][1] = r3;   // n group 2j+1
        }

#pragma unroll
        for (int mt = 0; mt < 2; mt++)
#pragma unroll
            for (int nt = 0; nt < 8; nt++)
                MMA16816(acc[mt][nt], a[mt][0], a[mt][1], a[mt][2], a[mt][3],
                         b[nt][0], b[nt][1]);
    }

    // Epilogue: direct coalesced float2 stores
    {
        int row_l = (l >> 2);
        int col_l = (l & 3) * 2;
#pragma unroll
        for (int mt = 0; mt < 2; mt++) {
            int r0 = gt0 + wm * 32 + mt * 16 + row_l;
            float* o0 = out + (size_t)r0 * EMBED + e0 + wn * 64 + col_l;
            float* o1 = out + (size_t)(r0 + 8) * EMBED + e0 + wn * 64 + col_l;
#pragma unroll
            for (int nt = 0; nt < 8; nt++) {
                *(float2*)(o0 + nt * 8) = make_float2(acc[mt][nt][0], acc[mt][nt][1]);
                *(float2*)(o1 + nt * 8) = make_float2(acc[mt][nt][2], acc[mt][nt][3]);
            }
        }
    }
}

// ---------------------------------------------------------------------------
extern "C" void kernel_launch(void* const* d_in, const int* in_sizes, int n_in,
                              void* d_out, int out_size)
{
    const float *x = nullptr, *theta = nullptr, *W1 = nullptr,
                *b1 = nullptr, *W2 = nullptr, *b2 = nullptr;
    for (int i = 0; i < n_in; i++) {
        switch (in_sizes[i]) {
            case NTOK * EMBED: x     = (const float*)d_in[i]; break;
            case NQ:           theta = (const float*)d_in[i]; break;
            case FFN * NQ:     W1    = (const float*)d_in[i]; break;
            case FFN:          b1    = (const float*)d_in[i]; break;
            case EMBED * FFN:  W2    = (const float*)d_in[i]; break;
            case EMBED:        b2    = (const float*)d_in[i]; break;
            default: break;
        }
    }
    float* out = (float*)d_out;

    static int smem_set = 0;
    if (!smem_set) {
        cudaFuncSetAttribute(gemm_hmma,
                             cudaFuncAttributeMaxDynamicSharedMemorySize,
                             SMEM_TOTAL);
        smem_set = 1;
    }

    h_kernel<<<NTOK / 256, 256>>>(x, theta, W1, b1);
    gemm_hmma<<<dim3(NTOK / MT, EMBED / NT), 256, SMEM_TOTAL>>>(W2, b2, out);
}